// round 5
// baseline (speedup 1.0000x reference)
#include <cuda_runtime.h>
#include <cuda_fp16.h>
#include <cstdint>

#define N_NODES 200000
#define DIM     64
#define NNZ_E   6400000
#define NE      (N_NODES * DIM)
#define SCAN_CHUNK 2048
#define SCAN_NBLK  ((N_NODES + SCAN_CHUNK - 1) / SCAN_CHUNK)   // 98
#define VAL_SCALE  524288.0f          // 32 * 16384
#define VAL_INV    (1.0f / 524288.0f)

// Scratch: __device__ globals (allocation-free rule). ~128 MB.
__device__ __half   g_h[NE];            // 25.6 MB  h = logmap0(x)
__device__ __half   g_m1[NE];           // 25.6 MB  m1 = A h
__device__ __half   g_m2[NE];           // 25.6 MB  m2 = A m1
__device__ __half   g_m3[NE];           // 25.6 MB  m3 = A m2
__device__ uint32_t g_cv[NNZ_E];        // 25.6 MB  packed: col<<14 | q14(val)
__device__ int      g_cnt[N_NODES];
__device__ int      g_rowptr[N_NODES + 1];
__device__ int      g_off[N_NODES];
__device__ int      g_blksum[SCAN_NBLK];

// ---------------------------------------------------------------------------
// Launch 0: logmap0 (c=1) -> fp16 h ; also zeroes histogram counters
// ---------------------------------------------------------------------------
__global__ void logmap_kernel(const float* __restrict__ x, __half2* __restrict__ h,
                              int* __restrict__ cnt) {
    int gi = blockIdx.x * blockDim.x + threadIdx.x;
    if (gi < N_NODES) cnt[gi] = 0;

    int row  = blockIdx.x * (blockDim.x >> 5) + (threadIdx.x >> 5);
    int lane = threadIdx.x & 31;
    if (row >= N_NODES) return;

    float2 v = reinterpret_cast<const float2*>(x + (size_t)row * DIM)[lane];
    float x0 = __shfl_sync(0xFFFFFFFFu, v.x, 0);
    float ss = v.y * v.y + (lane ? v.x * v.x : 0.0f);
    #pragma unroll
    for (int o = 16; o; o >>= 1) ss += __shfl_xor_sync(0xFFFFFFFFu, ss, o);

    float y_norm = fmaxf(sqrtf(ss), 1e-15f);
    float theta  = fmaxf(x0, 1.0f + 1e-7f);
    float s      = acoshf(theta) / y_norm;

    float2 o2;
    o2.x = lane ? s * v.x : 0.0f;
    o2.y = s * v.y;
    h[(size_t)row * 32 + lane] = __float22half2_rn(o2);
}

// ---------------------------------------------------------------------------
// Launch 1: histogram of row indices (int4 reads)
// ---------------------------------------------------------------------------
__global__ void hist_kernel(const int4* __restrict__ rows4, int* __restrict__ cnt) {
    int i = blockIdx.x * blockDim.x + threadIdx.x;
    for (; i < NNZ_E / 4; i += gridDim.x * blockDim.x) {
        int4 r = __ldg(rows4 + i);
        atomicAdd(&cnt[r.x], 1);
        atomicAdd(&cnt[r.y], 1);
        atomicAdd(&cnt[r.z], 1);
        atomicAdd(&cnt[r.w], 1);
    }
}

// ---------------------------------------------------------------------------
// Launch 2: per-block exclusive scan of 2048-chunks; totals -> blksum
// ---------------------------------------------------------------------------
__global__ void scan1_kernel(const int* __restrict__ cnt,
                             int* __restrict__ rowptr, int* __restrict__ blksum) {
    __shared__ int ws[32];
    __shared__ int carry_s;
    int tid = threadIdx.x, lane = tid & 31, wid = tid >> 5;
    int base0 = blockIdx.x * SCAN_CHUNK;
    if (tid == 0) carry_s = 0;
    __syncthreads();

    #pragma unroll
    for (int it = 0; it < SCAN_CHUNK / 1024; ++it) {
        int i = base0 + it * 1024 + tid;
        int v = (i < N_NODES) ? cnt[i] : 0;
        int x = v;
        #pragma unroll
        for (int o = 1; o < 32; o <<= 1) {
            int y = __shfl_up_sync(0xFFFFFFFFu, x, o);
            if (lane >= o) x += y;
        }
        if (lane == 31) ws[wid] = x;
        __syncthreads();
        if (wid == 0) {
            int s = ws[lane];
            #pragma unroll
            for (int o = 1; o < 32; o <<= 1) {
                int y = __shfl_up_sync(0xFFFFFFFFu, s, o);
                if (lane >= o) s += y;
            }
            ws[lane] = s;
        }
        __syncthreads();
        int carry = carry_s;
        int excl  = carry + (wid ? ws[wid - 1] : 0) + (x - v);
        if (i < N_NODES) rowptr[i] = excl;
        __syncthreads();
        if (tid == 0) carry_s = carry + ws[31];
        __syncthreads();
    }
    if (tid == 0) blksum[blockIdx.x] = carry_s;
}

// ---------------------------------------------------------------------------
// Launch 3: fused block-offset scan + apply
// ---------------------------------------------------------------------------
__global__ void scan3_kernel(int* __restrict__ rowptr, const int* __restrict__ blksum,
                             int* __restrict__ off) {
    __shared__ int boff[SCAN_NBLK];
    int tid = threadIdx.x, lane = tid & 31;
    if (tid < 32) {
        int carry = 0;
        for (int base = 0; base < SCAN_NBLK; base += 32) {
            int i = base + lane;
            int v = (i < SCAN_NBLK) ? blksum[i] : 0;
            int x = v;
            #pragma unroll
            for (int o = 1; o < 32; o <<= 1) {
                int y = __shfl_up_sync(0xFFFFFFFFu, x, o);
                if (lane >= o) x += y;
            }
            if (i < SCAN_NBLK) boff[i] = carry + x - v;
            carry += __shfl_sync(0xFFFFFFFFu, x, 31);
        }
    }
    __syncthreads();

    int i = blockIdx.x * blockDim.x + tid;
    for (; i < N_NODES; i += gridDim.x * blockDim.x) {
        int v = rowptr[i] + boff[i / SCAN_CHUNK];
        rowptr[i] = v;
        off[i]    = v;
    }
    if (blockIdx.x == 0 && tid == 0) rowptr[N_NODES] = NNZ_E;
}

// ---------------------------------------------------------------------------
// Launch 4: scatter packed (col<<14 | q14(val)) into row-grouped cv
// ---------------------------------------------------------------------------
__global__ void scatter_kernel(const int2* __restrict__ rows2, const int2* __restrict__ cols2,
                               const float2* __restrict__ vals2,
                               int* __restrict__ off, uint32_t* __restrict__ cv) {
    int i = blockIdx.x * blockDim.x + threadIdx.x;
    for (; i < NNZ_E / 2; i += gridDim.x * blockDim.x) {
        int2   r = __ldg(rows2 + i);
        int2   c = __ldg(cols2 + i);
        float2 v = __ldg(vals2 + i);
        uint32_t q0 = min((uint32_t)__float2int_rn(v.x * VAL_SCALE), 16383u);
        uint32_t q1 = min((uint32_t)__float2int_rn(v.y * VAL_SCALE), 16383u);
        int p0 = atomicAdd(&off[r.x], 1);
        cv[p0] = ((uint32_t)c.x << 14) | q0;
        int p1 = atomicAdd(&off[r.y], 1);
        cv[p1] = ((uint32_t)c.y << 14) | q1;
    }
}

// ---------------------------------------------------------------------------
// Launches 5-8: CSR SpMM  dst = A * src  (fp16 gather, fp32 accumulate)
// last layer fuses: out = 4*m1 + 5*m2 + 3*m3 + A*m3   (fp32)
// one warp per row; lane owns dims {2l,2l+1}; 16-wide batches incl. masked tail
// ---------------------------------------------------------------------------
__global__ void __launch_bounds__(256)
csr_spmm_kernel(const int* __restrict__ rowptr, const uint32_t* __restrict__ cv,
                const __half2* __restrict__ src, __half2* __restrict__ dst,
                const __half2* __restrict__ m1, const __half2* __restrict__ m2,
                const __half2* __restrict__ m3, float* __restrict__ out, int last) {
    int row  = blockIdx.x * 8 + (threadIdx.x >> 5);
    int lane = threadIdx.x & 31;
    if (row >= N_NODES) return;

    int beg = __ldg(rowptr + row);
    int end = __ldg(rowptr + row + 1);

    float ax = 0.0f, ay = 0.0f;
    int e = beg;

    // full 16-wide batches
    for (; e + 16 <= end; e += 16) {
        uint32_t w[16];
        #pragma unroll
        for (int k = 0; k < 16; ++k) w[k] = __ldg(cv + e + k);
        __half2 hh[16];
        #pragma unroll
        for (int k = 0; k < 16; ++k)
            hh[k] = __ldg(src + (size_t)(w[k] >> 14) * 32 + lane);
        #pragma unroll
        for (int k = 0; k < 16; ++k) {
            float2 p = __half22float2(hh[k]);
            float  v = (float)(w[k] & 0x3FFFu) * VAL_INV;
            ax = fmaf(v, p.x, ax);
            ay = fmaf(v, p.y, ay);
        }
    }
    // masked 16-wide tail (keeps loads in flight; OOB lanes clamp & zero val)
    if (e < end) {
        uint32_t w[16];
        #pragma unroll
        for (int k = 0; k < 16; ++k) {
            int idx = e + k < end ? e + k : end - 1;
            w[k] = __ldg(cv + idx);
        }
        __half2 hh[16];
        #pragma unroll
        for (int k = 0; k < 16; ++k)
            hh[k] = __ldg(src + (size_t)(w[k] >> 14) * 32 + lane);
        #pragma unroll
        for (int k = 0; k < 16; ++k) {
            float2 p = __half22float2(hh[k]);
            float  v = (e + k < end) ? (float)(w[k] & 0x3FFFu) * VAL_INV : 0.0f;
            ax = fmaf(v, p.x, ax);
            ay = fmaf(v, p.y, ay);
        }
    }

    size_t o = (size_t)row * 32 + lane;
    if (!last) {
        dst[o] = __float22half2_rn(make_float2(ax, ay));
    } else {
        float2 r1 = __half22float2(__ldg(m1 + o));
        float2 r2 = __half22float2(__ldg(m2 + o));
        float2 r3 = __half22float2(__ldg(m3 + o));
        float2 ov;
        ov.x = fmaf(4.0f, r1.x, fmaf(5.0f, r2.x, fmaf(3.0f, r3.x, ax)));
        ov.y = fmaf(4.0f, r1.y, fmaf(5.0f, r2.y, fmaf(3.0f, r3.y, ay)));
        reinterpret_cast<float2*>(out)[o] = ov;
    }
}

// ---------------------------------------------------------------------------
extern "C" void kernel_launch(void* const* d_in, const int* in_sizes, int n_in,
                              void* d_out, int out_size) {
    const float* x    = (const float*)d_in[0];
    const int*   rows = (const int*)  d_in[1];
    const int*   cols = (const int*)  d_in[2];
    const float* vals = (const float*)d_in[3];
    float*       out  = (float*)d_out;

    __half   *h, *m1, *m2, *m3;
    uint32_t *cv;
    int      *cnt, *rowptr, *off, *blksum;
    cudaGetSymbolAddress((void**)&h,      g_h);
    cudaGetSymbolAddress((void**)&m1,     g_m1);
    cudaGetSymbolAddress((void**)&m2,     g_m2);
    cudaGetSymbolAddress((void**)&m3,     g_m3);
    cudaGetSymbolAddress((void**)&cv,     g_cv);
    cudaGetSymbolAddress((void**)&cnt,    g_cnt);
    cudaGetSymbolAddress((void**)&rowptr, g_rowptr);
    cudaGetSymbolAddress((void**)&off,    g_off);
    cudaGetSymbolAddress((void**)&blksum, g_blksum);

    const int ROW_BLOCKS = (N_NODES + 7) / 8;   // 25000

    logmap_kernel<<<ROW_BLOCKS, 256>>>(x, (__half2*)h, cnt);
    hist_kernel<<<4096, 256>>>((const int4*)rows, cnt);
    scan1_kernel<<<SCAN_NBLK, 1024>>>(cnt, rowptr, blksum);
    scan3_kernel<<<256, 256>>>(rowptr, blksum, off);
    scatter_kernel<<<8192, 256>>>((const int2*)rows, (const int2*)cols,
                                  (const float2*)vals, off, cv);

    csr_spmm_kernel<<<ROW_BLOCKS, 256>>>(rowptr, cv, (__half2*)h,  (__half2*)m1,
                                         nullptr, nullptr, nullptr, nullptr, 0);
    csr_spmm_kernel<<<ROW_BLOCKS, 256>>>(rowptr, cv, (__half2*)m1, (__half2*)m2,
                                         nullptr, nullptr, nullptr, nullptr, 0);
    csr_spmm_kernel<<<ROW_BLOCKS, 256>>>(rowptr, cv, (__half2*)m2, (__half2*)m3,
                                         nullptr, nullptr, nullptr, nullptr, 0);
    csr_spmm_kernel<<<ROW_BLOCKS, 256>>>(rowptr, cv, (__half2*)m3, nullptr,
                                         (const __half2*)m1, (const __half2*)m2,
                                         (const __half2*)m3, out, 1);
}

// round 6
// speedup vs baseline: 1.3082x; 1.3082x over previous
#include <cuda_runtime.h>
#include <cuda_fp16.h>
#include <cstdint>

#define N_NODES 200000
#define DIM     64
#define NNZ_E   6400000
#define NE      (N_NODES * DIM)
#define SCAN_CHUNK 2048
#define SCAN_NBLK  ((N_NODES + SCAN_CHUNK - 1) / SCAN_CHUNK)   // 98
#define VAL_SCALE  524288.0f          // 32 * 16384
#define VAL_INV    (1.0f / 524288.0f)

// Scratch: __device__ globals (allocation-free rule). ~128 MB.
__device__ __half   g_h[NE];            // 25.6 MB  h = logmap0(x)
__device__ __half   g_m1[NE];           // 25.6 MB  m1 = A h
__device__ __half   g_m2[NE];           // 25.6 MB  m2 = A m1
__device__ __half   g_m3[NE];           // 25.6 MB  m3 = A m2
__device__ uint32_t g_cv[NNZ_E];        // 25.6 MB  packed: col<<14 | q14(val)
__device__ int      g_cnt[N_NODES];
__device__ int      g_rowptr[N_NODES + 1];
__device__ int      g_off[N_NODES];
__device__ int      g_blksum[SCAN_NBLK];

// ---------------------------------------------------------------------------
// Launch 0: logmap0 (c=1) -> fp16 h ; also zeroes histogram counters
// ---------------------------------------------------------------------------
__global__ void logmap_kernel(const float* __restrict__ x, __half2* __restrict__ h,
                              int* __restrict__ cnt) {
    int gi = blockIdx.x * blockDim.x + threadIdx.x;
    if (gi < N_NODES) cnt[gi] = 0;

    int row  = blockIdx.x * (blockDim.x >> 5) + (threadIdx.x >> 5);
    int lane = threadIdx.x & 31;
    if (row >= N_NODES) return;

    float2 v = reinterpret_cast<const float2*>(x + (size_t)row * DIM)[lane];
    float x0 = __shfl_sync(0xFFFFFFFFu, v.x, 0);
    float ss = v.y * v.y + (lane ? v.x * v.x : 0.0f);
    #pragma unroll
    for (int o = 16; o; o >>= 1) ss += __shfl_xor_sync(0xFFFFFFFFu, ss, o);

    float y_norm = fmaxf(sqrtf(ss), 1e-15f);
    float theta  = fmaxf(x0, 1.0f + 1e-7f);
    float s      = acoshf(theta) / y_norm;

    float2 o2;
    o2.x = lane ? s * v.x : 0.0f;
    o2.y = s * v.y;
    h[(size_t)row * 32 + lane] = __float22half2_rn(o2);
}

// ---------------------------------------------------------------------------
// Launch 1: histogram of row indices (int4 reads)
// ---------------------------------------------------------------------------
__global__ void hist_kernel(const int4* __restrict__ rows4, int* __restrict__ cnt) {
    int i = blockIdx.x * blockDim.x + threadIdx.x;
    for (; i < NNZ_E / 4; i += gridDim.x * blockDim.x) {
        int4 r = __ldg(rows4 + i);
        atomicAdd(&cnt[r.x], 1);
        atomicAdd(&cnt[r.y], 1);
        atomicAdd(&cnt[r.z], 1);
        atomicAdd(&cnt[r.w], 1);
    }
}

// ---------------------------------------------------------------------------
// Launch 2: per-block exclusive scan of 2048-chunks; totals -> blksum
// ---------------------------------------------------------------------------
__global__ void scan1_kernel(const int* __restrict__ cnt,
                             int* __restrict__ rowptr, int* __restrict__ blksum) {
    __shared__ int ws[32];
    __shared__ int carry_s;
    int tid = threadIdx.x, lane = tid & 31, wid = tid >> 5;
    int base0 = blockIdx.x * SCAN_CHUNK;
    if (tid == 0) carry_s = 0;
    __syncthreads();

    #pragma unroll
    for (int it = 0; it < SCAN_CHUNK / 1024; ++it) {
        int i = base0 + it * 1024 + tid;
        int v = (i < N_NODES) ? cnt[i] : 0;
        int x = v;
        #pragma unroll
        for (int o = 1; o < 32; o <<= 1) {
            int y = __shfl_up_sync(0xFFFFFFFFu, x, o);
            if (lane >= o) x += y;
        }
        if (lane == 31) ws[wid] = x;
        __syncthreads();
        if (wid == 0) {
            int s = ws[lane];
            #pragma unroll
            for (int o = 1; o < 32; o <<= 1) {
                int y = __shfl_up_sync(0xFFFFFFFFu, s, o);
                if (lane >= o) s += y;
            }
            ws[lane] = s;
        }
        __syncthreads();
        int carry = carry_s;
        int excl  = carry + (wid ? ws[wid - 1] : 0) + (x - v);
        if (i < N_NODES) rowptr[i] = excl;
        __syncthreads();
        if (tid == 0) carry_s = carry + ws[31];
        __syncthreads();
    }
    if (tid == 0) blksum[blockIdx.x] = carry_s;
}

// ---------------------------------------------------------------------------
// Launch 3: fused block-offset scan + apply
// ---------------------------------------------------------------------------
__global__ void scan3_kernel(int* __restrict__ rowptr, const int* __restrict__ blksum,
                             int* __restrict__ off) {
    __shared__ int boff[SCAN_NBLK];
    int tid = threadIdx.x, lane = tid & 31;
    if (tid < 32) {
        int carry = 0;
        for (int base = 0; base < SCAN_NBLK; base += 32) {
            int i = base + lane;
            int v = (i < SCAN_NBLK) ? blksum[i] : 0;
            int x = v;
            #pragma unroll
            for (int o = 1; o < 32; o <<= 1) {
                int y = __shfl_up_sync(0xFFFFFFFFu, x, o);
                if (lane >= o) x += y;
            }
            if (i < SCAN_NBLK) boff[i] = carry + x - v;
            carry += __shfl_sync(0xFFFFFFFFu, x, 31);
        }
    }
    __syncthreads();

    int i = blockIdx.x * blockDim.x + tid;
    for (; i < N_NODES; i += gridDim.x * blockDim.x) {
        int v = rowptr[i] + boff[i / SCAN_CHUNK];
        rowptr[i] = v;
        off[i]    = v;
    }
    if (blockIdx.x == 0 && tid == 0) rowptr[N_NODES] = NNZ_E;
}

// ---------------------------------------------------------------------------
// Launch 4: scatter packed (col<<14 | q14(val)) into row-grouped cv
// ---------------------------------------------------------------------------
__global__ void scatter_kernel(const int2* __restrict__ rows2, const int2* __restrict__ cols2,
                               const float2* __restrict__ vals2,
                               int* __restrict__ off, uint32_t* __restrict__ cv) {
    int i = blockIdx.x * blockDim.x + threadIdx.x;
    for (; i < NNZ_E / 2; i += gridDim.x * blockDim.x) {
        int2   r = __ldg(rows2 + i);
        int2   c = __ldg(cols2 + i);
        float2 v = __ldg(vals2 + i);
        uint32_t q0 = min((uint32_t)__float2int_rn(v.x * VAL_SCALE), 16383u);
        uint32_t q1 = min((uint32_t)__float2int_rn(v.y * VAL_SCALE), 16383u);
        int p0 = atomicAdd(&off[r.x], 1);
        cv[p0] = ((uint32_t)c.x << 14) | q0;
        int p1 = atomicAdd(&off[r.y], 1);
        cv[p1] = ((uint32_t)c.y << 14) | q1;
    }
}

// ---------------------------------------------------------------------------
// Launches 5-8: CSR SpMM  dst = A * src  (fp16 gather, fp32 accumulate)
// last layer fuses: out = 4*m1 + 5*m2 + 3*m3 + A*m3   (fp32)
// one warp per row; lane owns dims {2l,2l+1}; unroll-8 + scalar tail (R4 loop)
// ---------------------------------------------------------------------------
__global__ void __launch_bounds__(256)
csr_spmm_kernel(const int* __restrict__ rowptr, const uint32_t* __restrict__ cv,
                const __half2* __restrict__ src, __half2* __restrict__ dst,
                const __half2* __restrict__ m1, const __half2* __restrict__ m2,
                const __half2* __restrict__ m3, float* __restrict__ out, int last) {
    int row  = blockIdx.x * 8 + (threadIdx.x >> 5);
    int lane = threadIdx.x & 31;
    if (row >= N_NODES) return;

    int beg = __ldg(rowptr + row);
    int end = __ldg(rowptr + row + 1);

    float ax = 0.0f, ay = 0.0f;
    int e = beg;

    for (; e + 8 <= end; e += 8) {
        uint32_t w[8];
        #pragma unroll
        for (int k = 0; k < 8; ++k) w[k] = __ldg(cv + e + k);
        __half2 hh[8];
        #pragma unroll
        for (int k = 0; k < 8; ++k)
            hh[k] = __ldg(src + (size_t)(w[k] >> 14) * 32 + lane);
        #pragma unroll
        for (int k = 0; k < 8; ++k) {
            float2 p = __half22float2(hh[k]);
            float  v = (float)(w[k] & 0x3FFFu) * VAL_INV;
            ax = fmaf(v, p.x, ax);
            ay = fmaf(v, p.y, ay);
        }
    }
    for (; e < end; ++e) {
        uint32_t w = __ldg(cv + e);
        float2 p = __half22float2(__ldg(src + (size_t)(w >> 14) * 32 + lane));
        float v = (float)(w & 0x3FFFu) * VAL_INV;
        ax = fmaf(v, p.x, ax);
        ay = fmaf(v, p.y, ay);
    }

    size_t o = (size_t)row * 32 + lane;
    if (!last) {
        dst[o] = __float22half2_rn(make_float2(ax, ay));
    } else {
        float2 r1 = __half22float2(__ldg(m1 + o));
        float2 r2 = __half22float2(__ldg(m2 + o));
        float2 r3 = __half22float2(__ldg(m3 + o));
        float2 ov;
        ov.x = fmaf(4.0f, r1.x, fmaf(5.0f, r2.x, fmaf(3.0f, r3.x, ax)));
        ov.y = fmaf(4.0f, r1.y, fmaf(5.0f, r2.y, fmaf(3.0f, r3.y, ay)));
        reinterpret_cast<float2*>(out)[o] = ov;
    }
}

// ---------------------------------------------------------------------------
extern "C" void kernel_launch(void* const* d_in, const int* in_sizes, int n_in,
                              void* d_out, int out_size) {
    const float* x    = (const float*)d_in[0];
    const int*   rows = (const int*)  d_in[1];
    const int*   cols = (const int*)  d_in[2];
    const float* vals = (const float*)d_in[3];
    float*       out  = (float*)d_out;

    __half   *h, *m1, *m2, *m3;
    uint32_t *cv;
    int      *cnt, *rowptr, *off, *blksum;
    cudaGetSymbolAddress((void**)&h,      g_h);
    cudaGetSymbolAddress((void**)&m1,     g_m1);
    cudaGetSymbolAddress((void**)&m2,     g_m2);
    cudaGetSymbolAddress((void**)&m3,     g_m3);
    cudaGetSymbolAddress((void**)&cv,     g_cv);
    cudaGetSymbolAddress((void**)&cnt,    g_cnt);
    cudaGetSymbolAddress((void**)&rowptr, g_rowptr);
    cudaGetSymbolAddress((void**)&off,    g_off);
    cudaGetSymbolAddress((void**)&blksum, g_blksum);

    const int ROW_BLOCKS = (N_NODES + 7) / 8;   // 25000

    logmap_kernel<<<ROW_BLOCKS, 256>>>(x, (__half2*)h, cnt);
    hist_kernel<<<4096, 256>>>((const int4*)rows, cnt);
    scan1_kernel<<<SCAN_NBLK, 1024>>>(cnt, rowptr, blksum);
    scan3_kernel<<<256, 256>>>(rowptr, blksum, off);
    scatter_kernel<<<8192, 256>>>((const int2*)rows, (const int2*)cols,
                                  (const float2*)vals, off, cv);

    csr_spmm_kernel<<<ROW_BLOCKS, 256>>>(rowptr, cv, (__half2*)h,  (__half2*)m1,
                                         nullptr, nullptr, nullptr, nullptr, 0);
    csr_spmm_kernel<<<ROW_BLOCKS, 256>>>(rowptr, cv, (__half2*)m1, (__half2*)m2,
                                         nullptr, nullptr, nullptr, nullptr, 0);
    csr_spmm_kernel<<<ROW_BLOCKS, 256>>>(rowptr, cv, (__half2*)m2, (__half2*)m3,
                                         nullptr, nullptr, nullptr, nullptr, 0);
    csr_spmm_kernel<<<ROW_BLOCKS, 256>>>(rowptr, cv, (__half2*)m3, nullptr,
                                         (const __half2*)m1, (const __half2*)m2,
                                         (const __half2*)m3, out, 1);
}

// round 7
// speedup vs baseline: 1.5599x; 1.1924x over previous
#include <cuda_runtime.h>
#include <cuda_fp16.h>
#include <cstdint>

#define N_NODES 200000
#define DIM     64
#define NNZ_E   6400000
#define NE      (N_NODES * DIM)
#define SCAN_CHUNK 2048
#define SCAN_NBLK  ((N_NODES + SCAN_CHUNK - 1) / SCAN_CHUNK)   // 98

// Scratch: __device__ globals (allocation-free rule). ~154 MB.
__device__ __half g_h[NE];              // 25.6 MB  h = logmap0(x)
__device__ __half g_m1[NE];             // 25.6 MB  m1 = A h
__device__ __half g_m2[NE];             // 25.6 MB  m2 = A m1
__device__ __half g_m3[NE];             // 25.6 MB  m3 = A m2
__device__ int2   g_cv[NNZ_E];          // 51.2 MB  (col, val-bits) row-grouped
__device__ int    g_cnt[N_NODES];
__device__ int    g_rowptr[N_NODES + 1];
__device__ int    g_off[N_NODES];
__device__ int    g_blksum[SCAN_NBLK];

// ---------------------------------------------------------------------------
// Launch 0: logmap0 (c=1) -> fp16 h ; also zeroes histogram counters
// ---------------------------------------------------------------------------
__global__ void logmap_kernel(const float* __restrict__ x, __half2* __restrict__ h,
                              int* __restrict__ cnt) {
    int gi = blockIdx.x * blockDim.x + threadIdx.x;
    if (gi < N_NODES) cnt[gi] = 0;

    int row  = blockIdx.x * (blockDim.x >> 5) + (threadIdx.x >> 5);
    int lane = threadIdx.x & 31;
    if (row >= N_NODES) return;

    float2 v = reinterpret_cast<const float2*>(x + (size_t)row * DIM)[lane];
    float x0 = __shfl_sync(0xFFFFFFFFu, v.x, 0);
    float ss = v.y * v.y + (lane ? v.x * v.x : 0.0f);
    #pragma unroll
    for (int o = 16; o; o >>= 1) ss += __shfl_xor_sync(0xFFFFFFFFu, ss, o);

    float y_norm = fmaxf(sqrtf(ss), 1e-15f);
    float theta  = fmaxf(x0, 1.0f + 1e-7f);
    float s      = acoshf(theta) / y_norm;

    float2 o2;
    o2.x = lane ? s * v.x : 0.0f;
    o2.y = s * v.y;
    h[(size_t)row * 32 + lane] = __float22half2_rn(o2);
}

// ---------------------------------------------------------------------------
// Launch 1: histogram of row indices (int4 reads)
// ---------------------------------------------------------------------------
__global__ void hist_kernel(const int4* __restrict__ rows4, int* __restrict__ cnt) {
    int i = blockIdx.x * blockDim.x + threadIdx.x;
    for (; i < NNZ_E / 4; i += gridDim.x * blockDim.x) {
        int4 r = __ldg(rows4 + i);
        atomicAdd(&cnt[r.x], 1);
        atomicAdd(&cnt[r.y], 1);
        atomicAdd(&cnt[r.z], 1);
        atomicAdd(&cnt[r.w], 1);
    }
}

// ---------------------------------------------------------------------------
// Launch 2: per-block exclusive scan of 2048-chunks; totals -> blksum
// ---------------------------------------------------------------------------
__global__ void scan1_kernel(const int* __restrict__ cnt,
                             int* __restrict__ rowptr, int* __restrict__ blksum) {
    __shared__ int ws[32];
    __shared__ int carry_s;
    int tid = threadIdx.x, lane = tid & 31, wid = tid >> 5;
    int base0 = blockIdx.x * SCAN_CHUNK;
    if (tid == 0) carry_s = 0;
    __syncthreads();

    #pragma unroll
    for (int it = 0; it < SCAN_CHUNK / 1024; ++it) {
        int i = base0 + it * 1024 + tid;
        int v = (i < N_NODES) ? cnt[i] : 0;
        int x = v;
        #pragma unroll
        for (int o = 1; o < 32; o <<= 1) {
            int y = __shfl_up_sync(0xFFFFFFFFu, x, o);
            if (lane >= o) x += y;
        }
        if (lane == 31) ws[wid] = x;
        __syncthreads();
        if (wid == 0) {
            int s = ws[lane];
            #pragma unroll
            for (int o = 1; o < 32; o <<= 1) {
                int y = __shfl_up_sync(0xFFFFFFFFu, s, o);
                if (lane >= o) s += y;
            }
            ws[lane] = s;
        }
        __syncthreads();
        int carry = carry_s;
        int excl  = carry + (wid ? ws[wid - 1] : 0) + (x - v);
        if (i < N_NODES) rowptr[i] = excl;
        __syncthreads();
        if (tid == 0) carry_s = carry + ws[31];
        __syncthreads();
    }
    if (tid == 0) blksum[blockIdx.x] = carry_s;
}

// ---------------------------------------------------------------------------
// Launch 3: fused block-offset scan + apply
// ---------------------------------------------------------------------------
__global__ void scan3_kernel(int* __restrict__ rowptr, const int* __restrict__ blksum,
                             int* __restrict__ off) {
    __shared__ int boff[SCAN_NBLK];
    int tid = threadIdx.x, lane = tid & 31;
    if (tid < 32) {
        int carry = 0;
        for (int base = 0; base < SCAN_NBLK; base += 32) {
            int i = base + lane;
            int v = (i < SCAN_NBLK) ? blksum[i] : 0;
            int x = v;
            #pragma unroll
            for (int o = 1; o < 32; o <<= 1) {
                int y = __shfl_up_sync(0xFFFFFFFFu, x, o);
                if (lane >= o) x += y;
            }
            if (i < SCAN_NBLK) boff[i] = carry + x - v;
            carry += __shfl_sync(0xFFFFFFFFu, x, 31);
        }
    }
    __syncthreads();

    int i = blockIdx.x * blockDim.x + tid;
    for (; i < N_NODES; i += gridDim.x * blockDim.x) {
        int v = rowptr[i] + boff[i / SCAN_CHUNK];
        rowptr[i] = v;
        off[i]    = v;
    }
    if (blockIdx.x == 0 && tid == 0) rowptr[N_NODES] = NNZ_E;
}

// ---------------------------------------------------------------------------
// Launch 4: scatter (col,val) int2 into row-grouped cv; 2 edges/thread
// ---------------------------------------------------------------------------
__global__ void scatter_kernel(const int2* __restrict__ rows2, const int2* __restrict__ cols2,
                               const float2* __restrict__ vals2,
                               int* __restrict__ off, int2* __restrict__ cv) {
    int i = blockIdx.x * blockDim.x + threadIdx.x;
    for (; i < NNZ_E / 2; i += gridDim.x * blockDim.x) {
        int2   r = __ldg(rows2 + i);
        int2   c = __ldg(cols2 + i);
        float2 v = __ldg(vals2 + i);
        int p0 = atomicAdd(&off[r.x], 1);
        cv[p0] = make_int2(c.x, __float_as_int(v.x));
        int p1 = atomicAdd(&off[r.y], 1);
        cv[p1] = make_int2(c.y, __float_as_int(v.y));
    }
}

// ---------------------------------------------------------------------------
// Launches 5-8: CSR SpMM  dst = A * src  (fp16 gather, fp32 accumulate)
// Pairwise gather: lanes 0-15 handle edge e, lanes 16-31 handle edge e+1.
// Each lane loads 8 B (dims 4*(lane&15)..+3) -> 1 LDG.64 moves 2 feature rows.
// After the loop, shfl_xor(16) merges the two half-warp partial sums.
// last layer fuses: out = 4*m1 + 5*m2 + 3*m3 + A*m3   (fp32)
// ---------------------------------------------------------------------------
__global__ void __launch_bounds__(256)
csr_spmm_kernel(const int* __restrict__ rowptr, const int2* __restrict__ cv,
                const uint2* __restrict__ src, uint2* __restrict__ dst,
                const uint2* __restrict__ m1, const uint2* __restrict__ m2,
                const uint2* __restrict__ m3, float4* __restrict__ out, int last) {
    int row  = blockIdx.x * 8 + (threadIdx.x >> 5);
    int lane = threadIdx.x & 31;
    if (row >= N_NODES) return;

    int beg = __ldg(rowptr + row);
    int end = __ldg(rowptr + row + 1);

    int half = lane >> 4;    // which edge of the pair
    int sub  = lane & 15;    // which 4-dim group of the feature row

    float a0 = 0.f, a1 = 0.f, a2 = 0.f, a3 = 0.f;
    int e = beg;

    // 8 edges per iteration = 4 pairwise steps (MLP: 8 LDG.64 in flight)
    for (; e + 8 <= end; e += 8) {
        int2 w[4];
        #pragma unroll
        for (int k = 0; k < 4; ++k) w[k] = __ldg(cv + e + 2 * k + half);
        uint2 g[4];
        #pragma unroll
        for (int k = 0; k < 4; ++k)
            g[k] = __ldg(src + (size_t)w[k].x * 16 + sub);
        #pragma unroll
        for (int k = 0; k < 4; ++k) {
            float v = __int_as_float(w[k].y);
            float2 p0 = __half22float2(*reinterpret_cast<__half2*>(&g[k].x));
            float2 p1 = __half22float2(*reinterpret_cast<__half2*>(&g[k].y));
            a0 = fmaf(v, p0.x, a0); a1 = fmaf(v, p0.y, a1);
            a2 = fmaf(v, p1.x, a2); a3 = fmaf(v, p1.y, a3);
        }
    }
    // masked pairwise tail
    for (; e < end; e += 2) {
        int idx = e + half;
        int2 w = __ldg(cv + (idx < end ? idx : end - 1));
        float v = (idx < end) ? __int_as_float(w.y) : 0.0f;
        uint2 g = __ldg(src + (size_t)w.x * 16 + sub);
        float2 p0 = __half22float2(*reinterpret_cast<__half2*>(&g.x));
        float2 p1 = __half22float2(*reinterpret_cast<__half2*>(&g.y));
        a0 = fmaf(v, p0.x, a0); a1 = fmaf(v, p0.y, a1);
        a2 = fmaf(v, p1.x, a2); a3 = fmaf(v, p1.y, a3);
    }

    // merge the two half-warps (edge-parity partials for the same dims)
    a0 += __shfl_xor_sync(0xFFFFFFFFu, a0, 16);
    a1 += __shfl_xor_sync(0xFFFFFFFFu, a1, 16);
    a2 += __shfl_xor_sync(0xFFFFFFFFu, a2, 16);
    a3 += __shfl_xor_sync(0xFFFFFFFFu, a3, 16);

    if (half == 0) {
        size_t o = (size_t)row * 16 + sub;
        if (!last) {
            __half2 h0 = __float22half2_rn(make_float2(a0, a1));
            __half2 h1 = __float22half2_rn(make_float2(a2, a3));
            uint2 r;
            r.x = *reinterpret_cast<uint32_t*>(&h0);
            r.y = *reinterpret_cast<uint32_t*>(&h1);
            dst[o] = r;
        } else {
            uint2 q1 = __ldg(m1 + o);
            uint2 q2 = __ldg(m2 + o);
            uint2 q3 = __ldg(m3 + o);
            float2 r1a = __half22float2(*reinterpret_cast<__half2*>(&q1.x));
            float2 r1b = __half22float2(*reinterpret_cast<__half2*>(&q1.y));
            float2 r2a = __half22float2(*reinterpret_cast<__half2*>(&q2.x));
            float2 r2b = __half22float2(*reinterpret_cast<__half2*>(&q2.y));
            float2 r3a = __half22float2(*reinterpret_cast<__half2*>(&q3.x));
            float2 r3b = __half22float2(*reinterpret_cast<__half2*>(&q3.y));
            float4 ov;
            ov.x = fmaf(4.f, r1a.x, fmaf(5.f, r2a.x, fmaf(3.f, r3a.x, a0)));
            ov.y = fmaf(4.f, r1a.y, fmaf(5.f, r2a.y, fmaf(3.f, r3a.y, a1)));
            ov.z = fmaf(4.f, r1b.x, fmaf(5.f, r2b.x, fmaf(3.f, r3b.x, a2)));
            ov.w = fmaf(4.f, r1b.y, fmaf(5.f, r2b.y, fmaf(3.f, r3b.y, a3)));
            out[o] = ov;
        }
    }
}

// ---------------------------------------------------------------------------
extern "C" void kernel_launch(void* const* d_in, const int* in_sizes, int n_in,
                              void* d_out, int out_size) {
    const float* x    = (const float*)d_in[0];
    const int*   rows = (const int*)  d_in[1];
    const int*   cols = (const int*)  d_in[2];
    const float* vals = (const float*)d_in[3];
    float*       out  = (float*)d_out;

    __half *h, *m1, *m2, *m3;
    int2   *cv;
    int    *cnt, *rowptr, *off, *blksum;
    cudaGetSymbolAddress((void**)&h,      g_h);
    cudaGetSymbolAddress((void**)&m1,     g_m1);
    cudaGetSymbolAddress((void**)&m2,     g_m2);
    cudaGetSymbolAddress((void**)&m3,     g_m3);
    cudaGetSymbolAddress((void**)&cv,     g_cv);
    cudaGetSymbolAddress((void**)&cnt,    g_cnt);
    cudaGetSymbolAddress((void**)&rowptr, g_rowptr);
    cudaGetSymbolAddress((void**)&off,    g_off);
    cudaGetSymbolAddress((void**)&blksum, g_blksum);

    const int ROW_BLOCKS = (N_NODES + 7) / 8;   // 25000

    logmap_kernel<<<ROW_BLOCKS, 256>>>(x, (__half2*)h, cnt);
    hist_kernel<<<4096, 256>>>((const int4*)rows, cnt);
    scan1_kernel<<<SCAN_NBLK, 1024>>>(cnt, rowptr, blksum);
    scan3_kernel<<<256, 256>>>(rowptr, blksum, off);
    scatter_kernel<<<8192, 256>>>((const int2*)rows, (const int2*)cols,
                                  (const float2*)vals, off, cv);

    csr_spmm_kernel<<<ROW_BLOCKS, 256>>>(rowptr, cv, (const uint2*)h,  (uint2*)m1,
                                         nullptr, nullptr, nullptr, nullptr, 0);
    csr_spmm_kernel<<<ROW_BLOCKS, 256>>>(rowptr, cv, (const uint2*)m1, (uint2*)m2,
                                         nullptr, nullptr, nullptr, nullptr, 0);
    csr_spmm_kernel<<<ROW_BLOCKS, 256>>>(rowptr, cv, (const uint2*)m2, (uint2*)m3,
                                         nullptr, nullptr, nullptr, nullptr, 0);
    csr_spmm_kernel<<<ROW_BLOCKS, 256>>>(rowptr, cv, (const uint2*)m3, nullptr,
                                         (const uint2*)m1, (const uint2*)m2,
                                         (const uint2*)m3, (float4*)out, 1);
}